// round 1
// baseline (speedup 1.0000x reference)
#include <cuda_runtime.h>
#include <cuda_bf16.h>
#include <math.h>

// ---------------------------------------------------------------------------
// Problem constants
// ---------------------------------------------------------------------------
#define Bv   8
#define Tv   1024
#define Fv   64
#define DMv  256
#define Lv   4
#define DIv  512          // 2*DM
#define Nv   16
#define DCv  4
#define DTRv 16           // DM/16
#define BT   (Bv*Tv)      // 8192

// ---------------------------------------------------------------------------
// Scratch (device globals; no runtime allocation allowed)
// ---------------------------------------------------------------------------
__device__ float g_h  [BT * DMv];        //  8 MB  hidden between layers
__device__ float g_xz [BT * (2*DIv)];    // 32 MB  in_proj output (xc_raw | z)
__device__ float g_xc [BT * DIv];        // 16 MB  conv+silu output (u)
__device__ float g_dt [BT * DIv];        // 16 MB  softplus(dt)
__device__ float g_BC [BT * (2*Nv)];     //  1 MB  B (0..15) and C (16..31)
__device__ float g_y  [BT * DIv];        // 16 MB  gated scan output

// ---------------------------------------------------------------------------
// Generic fp32 GEMM:  C[M,N] = A[M,K] @ W[N,K]^T  (+ bias[n])
// 128x128 tile, BK=8, 256 threads, 8x8 per thread.
// Requires M%128==0, N%128==0, K%8==0 (true for all our shapes).
// ---------------------------------------------------------------------------
__global__ void __launch_bounds__(256)
sgemm_nt_kernel(const float* __restrict__ A, const float* __restrict__ W,
                float* __restrict__ C, const float* __restrict__ bias,
                int M, int N, int K)
{
    __shared__ float As[8][128];
    __shared__ float Bs[8][128];

    const int bm = blockIdx.y, bn = blockIdx.x;
    const int tid = threadIdx.x;
    const int lrow = tid >> 1;            // 0..127
    const int kq   = (tid & 1) << 2;      // 0 or 4

    const float* Ag = A + (size_t)(bm*128 + lrow) * K + kq;
    const float* Wg = W + (size_t)(bn*128 + lrow) * K + kq;

    const int tx = tid & 15, ty = tid >> 4;

    float acc[8][8];
#pragma unroll
    for (int i = 0; i < 8; ++i)
#pragma unroll
        for (int j = 0; j < 8; ++j) acc[i][j] = 0.f;

    for (int k0 = 0; k0 < K; k0 += 8) {
        float4 av = *(const float4*)(Ag + k0);
        float4 wv = *(const float4*)(Wg + k0);
        As[kq+0][lrow] = av.x; As[kq+1][lrow] = av.y;
        As[kq+2][lrow] = av.z; As[kq+3][lrow] = av.w;
        Bs[kq+0][lrow] = wv.x; Bs[kq+1][lrow] = wv.y;
        Bs[kq+2][lrow] = wv.z; Bs[kq+3][lrow] = wv.w;
        __syncthreads();

#pragma unroll
        for (int k = 0; k < 8; ++k) {
            float a[8], b[8];
            *(float4*)&a[0] = *(const float4*)&As[k][ty*8];
            *(float4*)&a[4] = *(const float4*)&As[k][ty*8 + 4];
            *(float4*)&b[0] = *(const float4*)&Bs[k][tx*8];
            *(float4*)&b[4] = *(const float4*)&Bs[k][tx*8 + 4];
#pragma unroll
            for (int i = 0; i < 8; ++i)
#pragma unroll
                for (int j = 0; j < 8; ++j)
                    acc[i][j] += a[i] * b[j];
        }
        __syncthreads();
    }

#pragma unroll
    for (int i = 0; i < 8; ++i) {
        const int m = bm*128 + ty*8 + i;
        float* Crow = C + (size_t)m * N + bn*128 + tx*8;
#pragma unroll
        for (int j = 0; j < 8; ++j) {
            float v = acc[i][j];
            if (bias) v += bias[bn*128 + tx*8 + j];
            Crow[j] = v;
        }
    }
}

// ---------------------------------------------------------------------------
// Fused middle kernel (per layer): causal conv(DC=4)+bias+SiLU  ->  x_proj
// (48 outs) -> dt_proj (512 outs) + softplus.  16 timesteps per block.
// grid = B * (T/16) = 512 blocks, 256 threads.
// ---------------------------------------------------------------------------
__global__ void __launch_bounds__(256)
fused_mid_kernel(const float* __restrict__ conv_w,  // [512][4]   layer slice
                 const float* __restrict__ conv_b,  // [512]
                 const float* __restrict__ xpw,     // [48][512]
                 const float* __restrict__ dtw,     // [512][16]
                 const float* __restrict__ dtb)     // [512]
{
    __shared__ float xc_s  [16][DIv];     // 32 KB
    __shared__ float wc_s  [48][66];      // ~12.4 KB (padded)
    __shared__ float xdbl_s[16][48];      // 3 KB

    const int blk = blockIdx.x;           // 0..511
    const int b   = blk >> 6;             // 64 chunks per batch
    const int t0  = (blk & 63) << 4;
    const int tid = threadIdx.x;

    // ---- conv + SiLU: each thread handles 2 channels across 16 timesteps --
#pragma unroll
    for (int dd = 0; dd < 2; ++dd) {
        const int d = tid + dd * 256;
        const float* xin = g_xz + (size_t)(b * Tv) * (2*DIv) + d; // xc_raw col d
        const float4 cw4 = *(const float4*)(conv_w + d*4);
        const float  cb  = conv_b[d];
        float x0 = (t0 - 3 >= 0) ? xin[(size_t)(t0-3) * (2*DIv)] : 0.f;
        float x1 = (t0 - 2 >= 0) ? xin[(size_t)(t0-2) * (2*DIv)] : 0.f;
        float x2 = (t0 - 1 >= 0) ? xin[(size_t)(t0-1) * (2*DIv)] : 0.f;
#pragma unroll
        for (int tt = 0; tt < 16; ++tt) {
            const float x3 = xin[(size_t)(t0+tt) * (2*DIv)];
            float s = cw4.x*x0 + cw4.y*x1 + cw4.z*x2 + cw4.w*x3 + cb;
            float sl = s / (1.f + __expf(-s));
            xc_s[tt][d] = sl;
            g_xc[((size_t)(b*Tv + t0 + tt)) * DIv + d] = sl;
            x0 = x1; x1 = x2; x2 = x3;
        }
    }
    __syncthreads();

    // ---- x_proj: xdbl[tt][o] = sum_k xc_s[tt][k]*xpw[o][k], o in 0..47 -----
    const int tt  = tid >> 4;     // 0..15
    const int oth = tid & 15;     // 0..15
    float acc0 = 0.f, acc1 = 0.f, acc2 = 0.f;

    for (int kc = 0; kc < DIv; kc += 64) {
        // stage weights chunk [48][64]
#pragma unroll
        for (int j = 0; j < 3; ++j) {
            const int l4 = tid * 3 + j;          // 0..767 float4s
            const int o  = l4 >> 4;              // 16 float4 per 64-wide row
            const int k  = (l4 & 15) << 2;
            const float4 v = *(const float4*)(xpw + o*DIv + kc + k);
            wc_s[o][k+0] = v.x; wc_s[o][k+1] = v.y;
            wc_s[o][k+2] = v.z; wc_s[o][k+3] = v.w;
        }
        __syncthreads();
#pragma unroll 8
        for (int k = 0; k < 64; ++k) {
            const float a = xc_s[tt][kc + k];
            acc0 += a * wc_s[oth      ][k];
            acc1 += a * wc_s[oth + 16][k];
            acc2 += a * wc_s[oth + 32][k];
        }
        __syncthreads();
    }
    xdbl_s[tt][oth     ] = acc0;
    xdbl_s[tt][oth + 16] = acc1;
    xdbl_s[tt][oth + 32] = acc2;
    __syncthreads();

    // ---- write B and C ------------------------------------------------------
    {
        int idx = tid;
#pragma unroll
        for (int r = 0; r < 2; ++r, idx += 256) {
            const int tti = idx >> 5, c = idx & 31;
            g_BC[((size_t)(b*Tv + t0 + tti)) * (2*Nv) + c] = xdbl_s[tti][16 + c];
        }
    }

    // ---- dt_proj + softplus -------------------------------------------------
#pragma unroll
    for (int dd = 0; dd < 2; ++dd) {
        const int d = tid + dd * 256;
        float w[16];
        *(float4*)&w[0]  = *(const float4*)(dtw + d*16 + 0);
        *(float4*)&w[4]  = *(const float4*)(dtw + d*16 + 4);
        *(float4*)&w[8]  = *(const float4*)(dtw + d*16 + 8);
        *(float4*)&w[12] = *(const float4*)(dtw + d*16 + 12);
        const float bia = dtb[d];
#pragma unroll
        for (int tt2 = 0; tt2 < 16; ++tt2) {
            float s = bia;
#pragma unroll
            for (int r = 0; r < 16; ++r) s += xdbl_s[tt2][r] * w[r];
            // stable softplus
            float sp = fmaxf(s, 0.f) + log1pf(__expf(-fabsf(s)));
            g_dt[((size_t)(b*Tv + t0 + tt2)) * DIv + d] = sp;
        }
    }
}

// ---------------------------------------------------------------------------
// Selective scan + D-skip + SiLU(z) gating.
// One warp handles 2 channels (16 lanes each, lane = state index n).
// 2048 warps total -> 256 blocks x 256 threads.
// ---------------------------------------------------------------------------
__global__ void __launch_bounds__(256)
scan_kernel(const float* __restrict__ A_log,   // [512][16] layer slice
            const float* __restrict__ Dp)      // [512]
{
    const int warp = blockIdx.x * 8 + (threadIdx.x >> 5);  // 0..2047
    const int lane = threadIdx.x & 31;
    const int b    = warp >> 8;           // 256 warps per batch
    const int dp   = warp & 255;
    const int half = lane >> 4;
    const int n    = lane & 15;
    const int d    = dp * 2 + half;

    const float a     = -__expf(A_log[d * Nv + n]);
    const float dcoef = Dp[d];
    float h = 0.f;

    const float* dtp = g_dt + (size_t)b * Tv * DIv + d;
    const float* up  = g_xc + (size_t)b * Tv * DIv + d;
    const float* zp  = g_xz + (size_t)b * Tv * (2*DIv) + DIv + d;
    const float* bcp = g_BC + (size_t)b * Tv * (2*Nv);
    float*       yp  = g_y  + (size_t)b * Tv * DIv + d;

#pragma unroll 4
    for (int t = 0; t < Tv; ++t) {
        const float dtv = dtp[(size_t)t * DIv];
        const float uv  = up [(size_t)t * DIv];
        const float bv  = bcp[t * (2*Nv) + n];
        const float cv  = bcp[t * (2*Nv) + Nv + n];

        const float dA = __expf(dtv * a);
        h = dA * h + (dtv * uv) * bv;

        float part = h * cv;
        part += __shfl_xor_sync(0xffffffffu, part, 1);
        part += __shfl_xor_sync(0xffffffffu, part, 2);
        part += __shfl_xor_sync(0xffffffffu, part, 4);
        part += __shfl_xor_sync(0xffffffffu, part, 8);

        if (n == 0) {
            const float zv = zp[(size_t)t * (2*DIv)];
            float y = part + dcoef * uv;
            y *= zv / (1.f + __expf(-zv));     // SiLU gate
            yp[(size_t)t * DIv] = y;
        }
    }
}

// ---------------------------------------------------------------------------
// Final: LayerNorm(last token) + head.  8 blocks (one per batch), 256 thr.
// ---------------------------------------------------------------------------
__global__ void __launch_bounds__(256)
final_kernel(const float* __restrict__ ln_g, const float* __restrict__ ln_b,
             const float* __restrict__ head_w, const float* __restrict__ head_b,
             float* __restrict__ out)
{
    __shared__ float red[256];
    const int b = blockIdx.x, tid = threadIdx.x;
    const float v = g_h[((size_t)(b * Tv + (Tv - 1))) * DMv + tid];

    red[tid] = v; __syncthreads();
    for (int s = 128; s > 0; s >>= 1) { if (tid < s) red[tid] += red[tid + s]; __syncthreads(); }
    const float mu = red[0] * (1.f / DMv);
    __syncthreads();

    const float dv = v - mu;
    red[tid] = dv * dv; __syncthreads();
    for (int s = 128; s > 0; s >>= 1) { if (tid < s) red[tid] += red[tid + s]; __syncthreads(); }
    const float var = red[0] * (1.f / DMv);
    __syncthreads();

    const float hn = dv * rsqrtf(var + 1e-5f) * ln_g[tid] + ln_b[tid];
    red[tid] = hn * head_w[tid]; __syncthreads();
    for (int s = 128; s > 0; s >>= 1) { if (tid < s) red[tid] += red[tid + s]; __syncthreads(); }
    if (tid == 0) out[b] = red[0] + head_b[0];
}

// ---------------------------------------------------------------------------
// Host launcher
// ---------------------------------------------------------------------------
extern "C" void kernel_launch(void* const* d_in, const int* in_sizes, int n_in,
                              void* d_out, int out_size)
{
    const float* x      = (const float*)d_in[0];   // (8,1024,64)
    const float* proj_w = (const float*)d_in[1];   // (256,64)
    const float* proj_b = (const float*)d_in[2];   // (256)
    const float* ipw    = (const float*)d_in[3];   // (4,1024,256)
    const float* cw     = (const float*)d_in[4];   // (4,512,4)
    const float* cb     = (const float*)d_in[5];   // (4,512)
    const float* xpw    = (const float*)d_in[6];   // (4,48,512)
    const float* dtw    = (const float*)d_in[7];   // (4,512,16)
    const float* dtb    = (const float*)d_in[8];   // (4,512)
    const float* A_log  = (const float*)d_in[9];   // (4,512,16)
    const float* Dp     = (const float*)d_in[10];  // (4,512)
    const float* opw    = (const float*)d_in[11];  // (4,256,512)
    const float* ln_g   = (const float*)d_in[12];  // (256)
    const float* ln_b   = (const float*)d_in[13];  // (256)
    const float* head_w = (const float*)d_in[14];  // (1,256)
    const float* head_b = (const float*)d_in[15];  // (1)
    float* out = (float*)d_out;

    float *hbuf, *xzbuf, *ybuf;
    cudaGetSymbolAddress((void**)&hbuf,  g_h);
    cudaGetSymbolAddress((void**)&xzbuf, g_xz);
    cudaGetSymbolAddress((void**)&ybuf,  g_y);

    // input projection: h = x @ proj_w^T + proj_b   [8192,256], K=64
    sgemm_nt_kernel<<<dim3(DMv/128, BT/128), 256>>>(x, proj_w, hbuf, proj_b,
                                                    BT, DMv, Fv);

    for (int l = 0; l < Lv; ++l) {
        // in_proj: xz = h @ ipw^T   [8192,1024], K=256
        sgemm_nt_kernel<<<dim3((2*DIv)/128, BT/128), 256>>>(
            hbuf, ipw + (size_t)l * (2*DIv) * DMv, xzbuf, nullptr,
            BT, 2*DIv, DMv);

        // conv + silu + x_proj + dt_proj(+softplus)
        fused_mid_kernel<<<Bv * (Tv/16), 256>>>(
            cw  + (size_t)l * DIv * DCv,
            cb  + (size_t)l * DIv,
            xpw + (size_t)l * (DTRv + 2*Nv) * DIv,
            dtw + (size_t)l * DIv * DTRv,
            dtb + (size_t)l * DIv);

        // selective scan + gating
        scan_kernel<<<256, 256>>>(A_log + (size_t)l * DIv * Nv,
                                  Dp    + (size_t)l * DIv);

        // out_proj: h = y @ opw^T   [8192,256], K=512
        sgemm_nt_kernel<<<dim3(DMv/128, BT/128), 256>>>(
            ybuf, opw + (size_t)l * DMv * DIv, hbuf, nullptr,
            BT, DMv, DIv);
    }

    final_kernel<<<Bv, 256>>>(ln_g, ln_b, head_w, head_b, out);
}

// round 4
// speedup vs baseline: 1.1370x; 1.1370x over previous
#include <cuda_runtime.h>
#include <cuda_bf16.h>
#include <mma.h>
#include <math.h>

using namespace nvcuda;

// ---------------------------------------------------------------------------
// Problem constants
// ---------------------------------------------------------------------------
#define Bv   8
#define Tv   1024
#define Fv   64
#define DMv  256
#define Lv   4
#define DIv  512          // 2*DM
#define Nv   16
#define DCv  4
#define DTRv 16           // DM/16
#define BT   (Bv*Tv)      // 8192

// ---------------------------------------------------------------------------
// Scratch (device globals; no runtime allocation allowed)
// ---------------------------------------------------------------------------
__device__ float g_h  [BT * DMv];
__device__ float g_xz [BT * (2*DIv)];
__device__ float g_xc [BT * DIv];
__device__ float g_dt [BT * DIv];
__device__ float g_BC [BT * (2*Nv)];
__device__ float g_y  [BT * DIv];

// split-bf16 weight buffers: proj_w[16384] | ipw[1048576] | opw[524288]
__device__ __nv_bfloat16 g_whi[1589248];
__device__ __nv_bfloat16 g_wlo[1589248];

// ---------------------------------------------------------------------------
// Weight split: fp32 -> (hi, lo) bf16
// ---------------------------------------------------------------------------
__global__ void __launch_bounds__(256)
split_kernel(const float* __restrict__ w, __nv_bfloat16* __restrict__ hi,
             __nv_bfloat16* __restrict__ lo, int n)
{
    int i = blockIdx.x * 256 + threadIdx.x;
    if (i < n) {
        float v = w[i];
        __nv_bfloat16 h = __float2bfloat16(v);
        hi[i] = h;
        lo[i] = __float2bfloat16(v - __bfloat162float(h));
    }
}

// ---------------------------------------------------------------------------
// Tensor-core GEMM via WMMA with fp32-emulation (2-term bf16 split).
// C[M,N] = A[M,K] @ W[N,K]^T.  A fp32 (split on the fly into shared),
// W pre-split bf16 hi/lo (fragments loaded straight from global).
// BM=BN=128, BK=32, 256 threads, 8 warps as 2(m) x 4(n),
// warp tile 64x32 = 4x2 wmma 16x16x16 fragments.
// Requires M%128==0, N%128==0, K%32==0.
// ---------------------------------------------------------------------------
#define SPAD 40

__global__ void __launch_bounds__(256)
wgemm_nt_kernel(const float* __restrict__ A,
                const __nv_bfloat16* __restrict__ Whi,
                const __nv_bfloat16* __restrict__ Wlo,
                float* __restrict__ C,
                int M, int N, int K)
{
    __shared__ __align__(32) __nv_bfloat16 Ah[128*SPAD];
    __shared__ __align__(32) __nv_bfloat16 Al[128*SPAD];

    const int tid = threadIdx.x;
    const int bm  = blockIdx.y, bn = blockIdx.x;
    const int wid = tid >> 5;
    const int wm  = wid >> 2;        // 0..1  -> 64 rows each
    const int wn  = wid & 3;         // 0..3  -> 32 cols each

    wmma::fragment<wmma::accumulator, 16, 16, 16, float> acc[4][2];
#pragma unroll
    for (int mi = 0; mi < 4; ++mi)
#pragma unroll
        for (int ni = 0; ni < 2; ++ni)
            wmma::fill_fragment(acc[mi][ni], 0.0f);

    for (int k0 = 0; k0 < K; k0 += 32) {
        // ---- stage A tile (fp32 -> hi/lo bf16) into shared ----------------
#pragma unroll
        for (int i = 0; i < 4; ++i) {
            const int idx = tid + i * 256;           // 0..1023 float4s
            const int row = idx >> 3;                // 8 float4 per 32-wide row
            const int kc  = (idx & 7) << 2;
            const float4 v = *(const float4*)(A + (size_t)(bm*128 + row) * K + k0 + kc);
            __nv_bfloat16 h0 = __float2bfloat16(v.x);
            __nv_bfloat16 h1 = __float2bfloat16(v.y);
            __nv_bfloat16 h2 = __float2bfloat16(v.z);
            __nv_bfloat16 h3 = __float2bfloat16(v.w);
            Ah[row*SPAD + kc + 0] = h0;
            Ah[row*SPAD + kc + 1] = h1;
            Ah[row*SPAD + kc + 2] = h2;
            Ah[row*SPAD + kc + 3] = h3;
            Al[row*SPAD + kc + 0] = __float2bfloat16(v.x - __bfloat162float(h0));
            Al[row*SPAD + kc + 1] = __float2bfloat16(v.y - __bfloat162float(h1));
            Al[row*SPAD + kc + 2] = __float2bfloat16(v.z - __bfloat162float(h2));
            Al[row*SPAD + kc + 3] = __float2bfloat16(v.w - __bfloat162float(h3));
        }
        __syncthreads();

#pragma unroll
        for (int ks = 0; ks < 32; ks += 16) {
            wmma::fragment<wmma::matrix_a, 16, 16, 16, __nv_bfloat16, wmma::row_major> aH[4], aL[4];
#pragma unroll
            for (int mi = 0; mi < 4; ++mi) {
                const int r0 = wm*64 + mi*16;
                wmma::load_matrix_sync(aH[mi], Ah + r0*SPAD + ks, SPAD);
                wmma::load_matrix_sync(aL[mi], Al + r0*SPAD + ks, SPAD);
            }
            // B = W^T (KxN); W row-major [N,K] => col_major with ldm=K
            wmma::fragment<wmma::matrix_b, 16, 16, 16, __nv_bfloat16, wmma::col_major> bH[2], bL[2];
#pragma unroll
            for (int ni = 0; ni < 2; ++ni) {
                const size_t off = (size_t)(bn*128 + wn*32 + ni*16) * K + k0 + ks;
                wmma::load_matrix_sync(bH[ni], Whi + off, K);
                wmma::load_matrix_sync(bL[ni], Wlo + off, K);
            }
#pragma unroll
            for (int mi = 0; mi < 4; ++mi)
#pragma unroll
                for (int ni = 0; ni < 2; ++ni) {
                    wmma::mma_sync(acc[mi][ni], aH[mi], bH[ni], acc[mi][ni]);
                    wmma::mma_sync(acc[mi][ni], aH[mi], bL[ni], acc[mi][ni]);
                    wmma::mma_sync(acc[mi][ni], aL[mi], bH[ni], acc[mi][ni]);
                }
        }
        __syncthreads();
    }

    // ---- epilogue: store accumulators straight to global ------------------
#pragma unroll
    for (int mi = 0; mi < 4; ++mi)
#pragma unroll
        for (int ni = 0; ni < 2; ++ni) {
            const int r0 = bm*128 + wm*64 + mi*16;
            const int c0 = bn*128 + wn*32 + ni*16;
            wmma::store_matrix_sync(C + (size_t)r0 * N + c0, acc[mi][ni], N,
                                    wmma::mem_row_major);
        }
}

// ---------------------------------------------------------------------------
// Elementwise bias add over [M, 256] (only used after the input projection).
// ---------------------------------------------------------------------------
__global__ void __launch_bounds__(256)
bias_add_kernel(float* __restrict__ C, const float* __restrict__ bias, int total)
{
    int i = blockIdx.x * 256 + threadIdx.x;
    if (i < total) C[i] += bias[i & 255];
}

// ---------------------------------------------------------------------------
// Fused middle kernel (per layer): conv(4)+bias+SiLU -> x_proj -> dt_proj
// + softplus.  16 timesteps per block, 512 blocks, 256 threads.
// ---------------------------------------------------------------------------
__global__ void __launch_bounds__(256)
fused_mid_kernel(const float* __restrict__ conv_w,
                 const float* __restrict__ conv_b,
                 const float* __restrict__ xpw,
                 const float* __restrict__ dtw,
                 const float* __restrict__ dtb)
{
    __shared__ float xc_s  [16][DIv];
    __shared__ float wc_s  [48][66];
    __shared__ float xdbl_s[16][48];

    const int blk = blockIdx.x;
    const int b   = blk >> 6;
    const int t0  = (blk & 63) << 4;
    const int tid = threadIdx.x;

#pragma unroll
    for (int dd = 0; dd < 2; ++dd) {
        const int d = tid + dd * 256;
        const float* xin = g_xz + (size_t)(b * Tv) * (2*DIv) + d;
        const float4 cw4 = *(const float4*)(conv_w + d*4);
        const float  cb  = conv_b[d];
        float x0 = (t0 - 3 >= 0) ? xin[(size_t)(t0-3) * (2*DIv)] : 0.f;
        float x1 = (t0 - 2 >= 0) ? xin[(size_t)(t0-2) * (2*DIv)] : 0.f;
        float x2 = (t0 - 1 >= 0) ? xin[(size_t)(t0-1) * (2*DIv)] : 0.f;
#pragma unroll
        for (int tt = 0; tt < 16; ++tt) {
            const float x3 = xin[(size_t)(t0+tt) * (2*DIv)];
            float s = cw4.x*x0 + cw4.y*x1 + cw4.z*x2 + cw4.w*x3 + cb;
            float sl = s / (1.f + __expf(-s));
            xc_s[tt][d] = sl;
            g_xc[((size_t)(b*Tv + t0 + tt)) * DIv + d] = sl;
            x0 = x1; x1 = x2; x2 = x3;
        }
    }
    __syncthreads();

    const int tt  = tid >> 4;
    const int oth = tid & 15;
    float acc0 = 0.f, acc1 = 0.f, acc2 = 0.f;

    for (int kc = 0; kc < DIv; kc += 64) {
#pragma unroll
        for (int j = 0; j < 3; ++j) {
            const int l4 = tid * 3 + j;
            const int o  = l4 >> 4;
            const int k  = (l4 & 15) << 2;
            const float4 v = *(const float4*)(xpw + o*DIv + kc + k);
            wc_s[o][k+0] = v.x; wc_s[o][k+1] = v.y;
            wc_s[o][k+2] = v.z; wc_s[o][k+3] = v.w;
        }
        __syncthreads();
#pragma unroll 8
        for (int k = 0; k < 64; ++k) {
            const float a = xc_s[tt][kc + k];
            acc0 += a * wc_s[oth      ][k];
            acc1 += a * wc_s[oth + 16][k];
            acc2 += a * wc_s[oth + 32][k];
        }
        __syncthreads();
    }
    xdbl_s[tt][oth     ] = acc0;
    xdbl_s[tt][oth + 16] = acc1;
    xdbl_s[tt][oth + 32] = acc2;
    __syncthreads();

    {
        int idx = tid;
#pragma unroll
        for (int r = 0; r < 2; ++r, idx += 256) {
            const int tti = idx >> 5, c = idx & 31;
            g_BC[((size_t)(b*Tv + t0 + tti)) * (2*Nv) + c] = xdbl_s[tti][16 + c];
        }
    }

#pragma unroll
    for (int dd = 0; dd < 2; ++dd) {
        const int d = tid + dd * 256;
        float w[16];
        *(float4*)&w[0]  = *(const float4*)(dtw + d*16 + 0);
        *(float4*)&w[4]  = *(const float4*)(dtw + d*16 + 4);
        *(float4*)&w[8]  = *(const float4*)(dtw + d*16 + 8);
        *(float4*)&w[12] = *(const float4*)(dtw + d*16 + 12);
        const float bia = dtb[d];
#pragma unroll
        for (int tt2 = 0; tt2 < 16; ++tt2) {
            float s = bia;
#pragma unroll
            for (int r = 0; r < 16; ++r) s += xdbl_s[tt2][r] * w[r];
            float sp = fmaxf(s, 0.f) + log1pf(__expf(-fabsf(s)));
            g_dt[((size_t)(b*Tv + t0 + tt2)) * DIv + d] = sp;
        }
    }
}

// ---------------------------------------------------------------------------
// Selective scan + D-skip + SiLU(z) gating.
// ---------------------------------------------------------------------------
__global__ void __launch_bounds__(256)
scan_kernel(const float* __restrict__ A_log, const float* __restrict__ Dp)
{
    const int warp = blockIdx.x * 8 + (threadIdx.x >> 5);
    const int lane = threadIdx.x & 31;
    const int b    = warp >> 8;
    const int dp   = warp & 255;
    const int half = lane >> 4;
    const int n    = lane & 15;
    const int d    = dp * 2 + half;

    const float a     = -__expf(A_log[d * Nv + n]);
    const float dcoef = Dp[d];
    float h = 0.f;

    const float* dtp = g_dt + (size_t)b * Tv * DIv + d;
    const float* up  = g_xc + (size_t)b * Tv * DIv + d;
    const float* zp  = g_xz + (size_t)b * Tv * (2*DIv) + DIv + d;
    const float* bcp = g_BC + (size_t)b * Tv * (2*Nv);
    float*       yp  = g_y  + (size_t)b * Tv * DIv + d;

#pragma unroll 4
    for (int t = 0; t < Tv; ++t) {
        const float dtv = dtp[(size_t)t * DIv];
        const float uv  = up [(size_t)t * DIv];
        const float bv  = bcp[t * (2*Nv) + n];
        const float cv  = bcp[t * (2*Nv) + Nv + n];

        const float dA = __expf(dtv * a);
        h = dA * h + (dtv * uv) * bv;

        float part = h * cv;
        part += __shfl_xor_sync(0xffffffffu, part, 1);
        part += __shfl_xor_sync(0xffffffffu, part, 2);
        part += __shfl_xor_sync(0xffffffffu, part, 4);
        part += __shfl_xor_sync(0xffffffffu, part, 8);

        if (n == 0) {
            const float zv = zp[(size_t)t * (2*DIv)];
            float y = part + dcoef * uv;
            y *= zv / (1.f + __expf(-zv));
            yp[(size_t)t * DIv] = y;
        }
    }
}

// ---------------------------------------------------------------------------
// Final: LayerNorm(last token) + head.
// ---------------------------------------------------------------------------
__global__ void __launch_bounds__(256)
final_kernel(const float* __restrict__ ln_g, const float* __restrict__ ln_b,
             const float* __restrict__ head_w, const float* __restrict__ head_b,
             float* __restrict__ out)
{
    __shared__ float red[256];
    const int b = blockIdx.x, tid = threadIdx.x;
    const float v = g_h[((size_t)(b * Tv + (Tv - 1))) * DMv + tid];

    red[tid] = v; __syncthreads();
    for (int s = 128; s > 0; s >>= 1) { if (tid < s) red[tid] += red[tid + s]; __syncthreads(); }
    const float mu = red[0] * (1.f / DMv);
    __syncthreads();

    const float dv = v - mu;
    red[tid] = dv * dv; __syncthreads();
    for (int s = 128; s > 0; s >>= 1) { if (tid < s) red[tid] += red[tid + s]; __syncthreads(); }
    const float var = red[0] * (1.f / DMv);
    __syncthreads();

    const float hn = dv * rsqrtf(var + 1e-5f) * ln_g[tid] + ln_b[tid];
    red[tid] = hn * head_w[tid]; __syncthreads();
    for (int s = 128; s > 0; s >>= 1) { if (tid < s) red[tid] += red[tid + s]; __syncthreads(); }
    if (tid == 0) out[b] = red[0] + head_b[0];
}

// ---------------------------------------------------------------------------
// Host launcher
// ---------------------------------------------------------------------------
extern "C" void kernel_launch(void* const* d_in, const int* in_sizes, int n_in,
                              void* d_out, int out_size)
{
    const float* x      = (const float*)d_in[0];
    const float* proj_w = (const float*)d_in[1];
    const float* proj_b = (const float*)d_in[2];
    const float* ipw    = (const float*)d_in[3];
    const float* cw     = (const float*)d_in[4];
    const float* cb     = (const float*)d_in[5];
    const float* xpw    = (const float*)d_in[6];
    const float* dtw    = (const float*)d_in[7];
    const float* dtb    = (const float*)d_in[8];
    const float* A_log  = (const float*)d_in[9];
    const float* Dp     = (const float*)d_in[10];
    const float* opw    = (const float*)d_in[11];
    const float* ln_g   = (const float*)d_in[12];
    const float* ln_b   = (const float*)d_in[13];
    const float* head_w = (const float*)d_in[14];
    const float* head_b = (const float*)d_in[15];
    float* out = (float*)d_out;

    float *hbuf, *xzbuf, *ybuf;
    __nv_bfloat16 *whi, *wlo;
    cudaGetSymbolAddress((void**)&hbuf,  g_h);
    cudaGetSymbolAddress((void**)&xzbuf, g_xz);
    cudaGetSymbolAddress((void**)&ybuf,  g_y);
    cudaGetSymbolAddress((void**)&whi,   g_whi);
    cudaGetSymbolAddress((void**)&wlo,   g_wlo);

    __nv_bfloat16* whi_proj = whi;
    __nv_bfloat16* wlo_proj = wlo;
    __nv_bfloat16* whi_ipw  = whi + 16384;
    __nv_bfloat16* wlo_ipw  = wlo + 16384;
    __nv_bfloat16* whi_opw  = whi + 1064960;
    __nv_bfloat16* wlo_opw  = wlo + 1064960;

    // split weights into bf16 hi/lo (sizes are exact multiples of 256)
    split_kernel<<<64, 256>>>(proj_w, whi_proj, wlo_proj, 16384);
    split_kernel<<<4096, 256>>>(ipw, whi_ipw, wlo_ipw, 1048576);
    split_kernel<<<2048, 256>>>(opw, whi_opw, wlo_opw, 524288);

    dim3 grid_in(2, 64);      // N=256/128,  M=8192/128
    dim3 grid_ip(8, 64);      // N=1024/128
    dim3 grid_op(2, 64);      // N=256/128

    // input projection: h = x @ proj_w^T + proj_b   [8192,256], K=64
    wgemm_nt_kernel<<<grid_in, 256>>>(x, whi_proj, wlo_proj, hbuf, BT, DMv, Fv);
    bias_add_kernel<<<8192, 256>>>(hbuf, proj_b, BT * DMv);

    for (int l = 0; l < Lv; ++l) {
        const size_t ipoff = (size_t)l * 262144;   // (2*DIv)*DMv
        const size_t opoff = (size_t)l * 131072;   // DMv*DIv

        // in_proj: xz = h @ ipw^T   [8192,1024], K=256
        wgemm_nt_kernel<<<grid_ip, 256>>>(hbuf, whi_ipw + ipoff, wlo_ipw + ipoff,
                                          xzbuf, BT, 2*DIv, DMv);

        fused_mid_kernel<<<512, 256>>>(
            cw  + (size_t)l * DIv * DCv,
            cb  + (size_t)l * DIv,
            xpw + (size_t)l * (DTRv + 2*Nv) * DIv,
            dtw + (size_t)l * DIv * DTRv,
            dtb + (size_t)l * DIv);

        scan_kernel<<<256, 256>>>(A_log + (size_t)l * DIv * Nv,
                                  Dp    + (size_t)l * DIv);

        // out_proj: h = y @ opw^T   [8192,256], K=512
        wgemm_nt_kernel<<<grid_op, 256>>>(ybuf, whi_opw + opoff, wlo_opw + opoff,
                                          hbuf, BT, DMv, DIv);
    }

    final_kernel<<<Bv, 256>>>(ln_g, ln_b, head_w, head_b, out);
}

// round 5
// speedup vs baseline: 2.7339x; 2.4045x over previous
#include <cuda_runtime.h>
#include <cuda_bf16.h>
#include <mma.h>
#include <math.h>

using namespace nvcuda;

// ---------------------------------------------------------------------------
// Problem constants
// ---------------------------------------------------------------------------
#define Bv   8
#define Tv   1024
#define Fv   64
#define DMv  256
#define Lv   4
#define DIv  512          // 2*DM
#define Nv   16
#define DCv  4
#define DTRv 16           // DM/16
#define BT   (Bv*Tv)      // 8192

// ---------------------------------------------------------------------------
// Scratch (device globals; no runtime allocation allowed)
// ---------------------------------------------------------------------------
__device__ float g_h  [BT * DMv];        // hidden (fp32, for final LN)
__device__ float g_xz [BT * (2*DIv)];    // in_proj output (xc_raw | z)
__device__ float g_xc [BT * DIv];        // conv+silu output (u)
__device__ float g_dt [BT * DIv];        // softplus(dt)
__device__ float g_BC [BT * (2*Nv)];     // B | C

// bf16 hi/lo activation buffers (GEMM A operands)
__device__ __nv_bfloat16 g_xhi[BT * Fv],  g_xlo[BT * Fv];
__device__ __nv_bfloat16 g_hhi[BT * DMv], g_hlo[BT * DMv];
__device__ __nv_bfloat16 g_yhi[BT * DIv], g_ylo[BT * DIv];

// split-bf16 weight buffers: proj_w[16384] | ipw[1048576] | opw[524288]
__device__ __nv_bfloat16 g_whi[1589248];
__device__ __nv_bfloat16 g_wlo[1589248];

// ---------------------------------------------------------------------------
// Split: fp32 -> (hi, lo) bf16
// ---------------------------------------------------------------------------
__global__ void __launch_bounds__(256)
split_kernel(const float* __restrict__ w, __nv_bfloat16* __restrict__ hi,
             __nv_bfloat16* __restrict__ lo, int n)
{
    int i = blockIdx.x * 256 + threadIdx.x;
    if (i < n) {
        float v = w[i];
        __nv_bfloat16 h = __float2bfloat16(v);
        hi[i] = h;
        lo[i] = __float2bfloat16(v - __bfloat162float(h));
    }
}

// ---------------------------------------------------------------------------
// Tensor-core GEMM, fp32 emulation via 2-term bf16 split; all operands
// pre-split bf16 hi/lo.  C[M,N] = A[M,K] @ W[N,K]^T.
// BM=BN=128, BK=32, 256 threads, 8 warps as 2(m) x 4(n),
// warp tile 64x32 = 4x2 wmma 16x16x16 fragments.  A and B staged in smem.
// Requires M%128==0, N%128==0, K%32==0.
// ---------------------------------------------------------------------------
#define SPAD 40

__global__ void __launch_bounds__(256)
wgemm_nt_kernel(const __nv_bfloat16* __restrict__ Ahi,
                const __nv_bfloat16* __restrict__ Alo,
                const __nv_bfloat16* __restrict__ Whi,
                const __nv_bfloat16* __restrict__ Wlo,
                float* __restrict__ C,
                int M, int N, int K)
{
    __shared__ __align__(16) __nv_bfloat16 Ah[128*SPAD];
    __shared__ __align__(16) __nv_bfloat16 Al[128*SPAD];
    __shared__ __align__(16) __nv_bfloat16 Bh[128*SPAD];
    __shared__ __align__(16) __nv_bfloat16 Bl[128*SPAD];

    const int tid = threadIdx.x;
    const int bm  = blockIdx.y, bn = blockIdx.x;
    const int wid = tid >> 5;
    const int wm  = wid >> 2;        // 0..1  -> 64 rows each
    const int wn  = wid & 3;         // 0..3  -> 32 cols each

    wmma::fragment<wmma::accumulator, 16, 16, 16, float> acc[4][2];
#pragma unroll
    for (int mi = 0; mi < 4; ++mi)
#pragma unroll
        for (int ni = 0; ni < 2; ++ni)
            wmma::fill_fragment(acc[mi][ni], 0.0f);

    for (int k0 = 0; k0 < K; k0 += 32) {
        // ---- stage A and B tiles (bf16, float4 = 8 elements) --------------
#pragma unroll
        for (int i = 0; i < 2; ++i) {
            const int idx = tid + i * 256;       // 0..511 float4s
            const int row = idx >> 2;            // 4 float4 per 32-wide row
            const int kc  = (idx & 3) << 3;
            const size_t ga = (size_t)(bm*128 + row) * K + k0 + kc;
            const size_t gb = (size_t)(bn*128 + row) * K + k0 + kc;
            *(float4*)(Ah + row*SPAD + kc) = *(const float4*)(Ahi + ga);
            *(float4*)(Al + row*SPAD + kc) = *(const float4*)(Alo + ga);
            *(float4*)(Bh + row*SPAD + kc) = *(const float4*)(Whi + gb);
            *(float4*)(Bl + row*SPAD + kc) = *(const float4*)(Wlo + gb);
        }
        __syncthreads();

#pragma unroll
        for (int ks = 0; ks < 32; ks += 16) {
            wmma::fragment<wmma::matrix_a, 16, 16, 16, __nv_bfloat16, wmma::row_major> aH[4], aL[4];
#pragma unroll
            for (int mi = 0; mi < 4; ++mi) {
                const int r0 = wm*64 + mi*16;
                wmma::load_matrix_sync(aH[mi], Ah + r0*SPAD + ks, SPAD);
                wmma::load_matrix_sync(aL[mi], Al + r0*SPAD + ks, SPAD);
            }
            wmma::fragment<wmma::matrix_b, 16, 16, 16, __nv_bfloat16, wmma::col_major> bH[2], bL[2];
#pragma unroll
            for (int ni = 0; ni < 2; ++ni) {
                const int r0 = wn*32 + ni*16;
                wmma::load_matrix_sync(bH[ni], Bh + r0*SPAD + ks, SPAD);
                wmma::load_matrix_sync(bL[ni], Bl + r0*SPAD + ks, SPAD);
            }
#pragma unroll
            for (int mi = 0; mi < 4; ++mi)
#pragma unroll
                for (int ni = 0; ni < 2; ++ni) {
                    wmma::mma_sync(acc[mi][ni], aH[mi], bH[ni], acc[mi][ni]);
                    wmma::mma_sync(acc[mi][ni], aH[mi], bL[ni], acc[mi][ni]);
                    wmma::mma_sync(acc[mi][ni], aL[mi], bH[ni], acc[mi][ni]);
                }
        }
        __syncthreads();
    }

#pragma unroll
    for (int mi = 0; mi < 4; ++mi)
#pragma unroll
        for (int ni = 0; ni < 2; ++ni) {
            const int r0 = bm*128 + wm*64 + mi*16;
            const int c0 = bn*128 + wn*32 + ni*16;
            wmma::store_matrix_sync(C + (size_t)r0 * N + c0, acc[mi][ni], N,
                                    wmma::mem_row_major);
        }
}

// ---------------------------------------------------------------------------
// Bias add over [M, 256]
// ---------------------------------------------------------------------------
__global__ void __launch_bounds__(256)
bias_add_kernel(float* __restrict__ C, const float* __restrict__ bias, int total)
{
    int i = blockIdx.x * 256 + threadIdx.x;
    if (i < total) C[i] += bias[i & 255];
}

// ---------------------------------------------------------------------------
// Fused middle kernel (per layer): conv(4)+bias+SiLU -> x_proj -> dt_proj
// + softplus.  16 timesteps per block, 512 blocks, 256 threads.
// ---------------------------------------------------------------------------
__global__ void __launch_bounds__(256)
fused_mid_kernel(const float* __restrict__ conv_w,
                 const float* __restrict__ conv_b,
                 const float* __restrict__ xpw,
                 const float* __restrict__ dtw,
                 const float* __restrict__ dtb)
{
    __shared__ float xc_s  [16][DIv];
    __shared__ float wc_s  [48][66];
    __shared__ float xdbl_s[16][48];

    const int blk = blockIdx.x;
    const int b   = blk >> 6;
    const int t0  = (blk & 63) << 4;
    const int tid = threadIdx.x;

#pragma unroll
    for (int dd = 0; dd < 2; ++dd) {
        const int d = tid + dd * 256;
        const float* xin = g_xz + (size_t)(b * Tv) * (2*DIv) + d;
        const float4 cw4 = *(const float4*)(conv_w + d*4);
        const float  cb  = conv_b[d];
        float x0 = (t0 - 3 >= 0) ? xin[(size_t)(t0-3) * (2*DIv)] : 0.f;
        float x1 = (t0 - 2 >= 0) ? xin[(size_t)(t0-2) * (2*DIv)] : 0.f;
        float x2 = (t0 - 1 >= 0) ? xin[(size_t)(t0-1) * (2*DIv)] : 0.f;
#pragma unroll
        for (int tt = 0; tt < 16; ++tt) {
            const float x3 = xin[(size_t)(t0+tt) * (2*DIv)];
            float s = cw4.x*x0 + cw4.y*x1 + cw4.z*x2 + cw4.w*x3 + cb;
            float sl = s / (1.f + __expf(-s));
            xc_s[tt][d] = sl;
            g_xc[((size_t)(b*Tv + t0 + tt)) * DIv + d] = sl;
            x0 = x1; x1 = x2; x2 = x3;
        }
    }
    __syncthreads();

    const int tt  = tid >> 4;
    const int oth = tid & 15;
    float acc0 = 0.f, acc1 = 0.f, acc2 = 0.f;

    for (int kc = 0; kc < DIv; kc += 64) {
#pragma unroll
        for (int j = 0; j < 3; ++j) {
            const int l4 = tid * 3 + j;
            const int o  = l4 >> 4;
            const int k  = (l4 & 15) << 2;
            const float4 v = *(const float4*)(xpw + o*DIv + kc + k);
            wc_s[o][k+0] = v.x; wc_s[o][k+1] = v.y;
            wc_s[o][k+2] = v.z; wc_s[o][k+3] = v.w;
        }
        __syncthreads();
#pragma unroll 8
        for (int k = 0; k < 64; ++k) {
            const float a = xc_s[tt][kc + k];
            acc0 += a * wc_s[oth      ][k];
            acc1 += a * wc_s[oth + 16][k];
            acc2 += a * wc_s[oth + 32][k];
        }
        __syncthreads();
    }
    xdbl_s[tt][oth     ] = acc0;
    xdbl_s[tt][oth + 16] = acc1;
    xdbl_s[tt][oth + 32] = acc2;
    __syncthreads();

    {
        int idx = tid;
#pragma unroll
        for (int r = 0; r < 2; ++r, idx += 256) {
            const int tti = idx >> 5, c = idx & 31;
            g_BC[((size_t)(b*Tv + t0 + tti)) * (2*Nv) + c] = xdbl_s[tti][16 + c];
        }
    }

#pragma unroll
    for (int dd = 0; dd < 2; ++dd) {
        const int d = tid + dd * 256;
        float w[16];
        *(float4*)&w[0]  = *(const float4*)(dtw + d*16 + 0);
        *(float4*)&w[4]  = *(const float4*)(dtw + d*16 + 4);
        *(float4*)&w[8]  = *(const float4*)(dtw + d*16 + 8);
        *(float4*)&w[12] = *(const float4*)(dtw + d*16 + 12);
        const float bia = dtb[d];
#pragma unroll
        for (int tt2 = 0; tt2 < 16; ++tt2) {
            float s = bia;
#pragma unroll
            for (int r = 0; r < 16; ++r) s += xdbl_s[tt2][r] * w[r];
            float sp = fmaxf(s, 0.f) + log1pf(__expf(-fabsf(s)));
            g_dt[((size_t)(b*Tv + t0 + tt2)) * DIv + d] = sp;
        }
    }
}

// ---------------------------------------------------------------------------
// Selective scan v2: smem-chunked.  Block = (b, 16-channel group), 256 thr.
// Warp handles 2 channels (16 lanes each, lane = state n).  Chunks of 64 t
// staged coalesced into smem; inner loop reads smem only.  Output y written
// directly as bf16 hi/lo for the out_proj GEMM.
// grid = (32, 8): x = channel group, y = batch.
// ---------------------------------------------------------------------------
__global__ void __launch_bounds__(256)
scan2_kernel(const float* __restrict__ A_log, const float* __restrict__ Dp)
{
    __shared__ float s_dt[64][16];
    __shared__ float s_u [64][16];
    __shared__ float s_z [64][16];
    __shared__ float s_bc[64][32];

    const int d0   = blockIdx.x * 16;
    const int b    = blockIdx.y;
    const int tid  = threadIdx.x;
    const int warp = tid >> 5;
    const int lane = tid & 31;
    const int half = lane >> 4;
    const int n    = lane & 15;
    const int dloc = warp * 2 + half;      // 0..15
    const int d    = d0 + dloc;

    const float a     = -__expf(A_log[d * Nv + n]);
    const float dcoef = Dp[d];
    float h = 0.f;

    for (int tc = 0; tc < Tv; tc += 64) {
        const int base = b * Tv + tc;
        // ---- stage chunk ---------------------------------------------------
#pragma unroll
        for (int i = 0; i < 4; ++i) {
            const int idx = tid + i * 256;        // 0..1023
            const int tt  = idx >> 4;
            const int dd  = idx & 15;
            s_dt[tt][dd] = g_dt[(size_t)(base + tt) * DIv + d0 + dd];
            s_u [tt][dd] = g_xc[(size_t)(base + tt) * DIv + d0 + dd];
            s_z [tt][dd] = g_xz[(size_t)(base + tt) * (2*DIv) + DIv + d0 + dd];
        }
#pragma unroll
        for (int i = 0; i < 8; ++i) {
            const int idx = tid + i * 256;        // 0..2047
            const int tt  = idx >> 5;
            const int c   = idx & 31;
            s_bc[tt][c] = g_BC[(size_t)(base + tt) * (2*Nv) + c];
        }
        __syncthreads();

        // ---- scan 64 timesteps from smem -----------------------------------
#pragma unroll 4
        for (int tt = 0; tt < 64; ++tt) {
            const float dtv = s_dt[tt][dloc];
            const float uv  = s_u [tt][dloc];
            const float bv  = s_bc[tt][n];
            const float cv  = s_bc[tt][Nv + n];

            const float dA = __expf(dtv * a);
            h = dA * h + (dtv * uv) * bv;

            float part = h * cv;
            part += __shfl_xor_sync(0xffffffffu, part, 1);
            part += __shfl_xor_sync(0xffffffffu, part, 2);
            part += __shfl_xor_sync(0xffffffffu, part, 4);
            part += __shfl_xor_sync(0xffffffffu, part, 8);

            if (n == 0) {
                const float zv = s_z[tt][dloc];
                float y = part + dcoef * uv;
                y *= zv / (1.f + __expf(-zv));
                __nv_bfloat16 yh = __float2bfloat16(y);
                const size_t o = (size_t)(base + tt) * DIv + d;
                g_yhi[o] = yh;
                g_ylo[o] = __float2bfloat16(y - __bfloat162float(yh));
            }
        }
        __syncthreads();
    }
}

// ---------------------------------------------------------------------------
// Final: LayerNorm(last token) + head.
// ---------------------------------------------------------------------------
__global__ void __launch_bounds__(256)
final_kernel(const float* __restrict__ ln_g, const float* __restrict__ ln_b,
             const float* __restrict__ head_w, const float* __restrict__ head_b,
             float* __restrict__ out)
{
    __shared__ float red[256];
    const int b = blockIdx.x, tid = threadIdx.x;
    const float v = g_h[((size_t)(b * Tv + (Tv - 1))) * DMv + tid];

    red[tid] = v; __syncthreads();
    for (int s = 128; s > 0; s >>= 1) { if (tid < s) red[tid] += red[tid + s]; __syncthreads(); }
    const float mu = red[0] * (1.f / DMv);
    __syncthreads();

    const float dv = v - mu;
    red[tid] = dv * dv; __syncthreads();
    for (int s = 128; s > 0; s >>= 1) { if (tid < s) red[tid] += red[tid + s]; __syncthreads(); }
    const float var = red[0] * (1.f / DMv);
    __syncthreads();

    const float hn = dv * rsqrtf(var + 1e-5f) * ln_g[tid] + ln_b[tid];
    red[tid] = hn * head_w[tid]; __syncthreads();
    for (int s = 128; s > 0; s >>= 1) { if (tid < s) red[tid] += red[tid + s]; __syncthreads(); }
    if (tid == 0) out[b] = red[0] + head_b[0];
}

// ---------------------------------------------------------------------------
// Host launcher
// ---------------------------------------------------------------------------
extern "C" void kernel_launch(void* const* d_in, const int* in_sizes, int n_in,
                              void* d_out, int out_size)
{
    const float* x      = (const float*)d_in[0];
    const float* proj_w = (const float*)d_in[1];
    const float* proj_b = (const float*)d_in[2];
    const float* ipw    = (const float*)d_in[3];
    const float* cw     = (const float*)d_in[4];
    const float* cb     = (const float*)d_in[5];
    const float* xpw    = (const float*)d_in[6];
    const float* dtw    = (const float*)d_in[7];
    const float* dtb    = (const float*)d_in[8];
    const float* A_log  = (const float*)d_in[9];
    const float* Dp     = (const float*)d_in[10];
    const float* opw    = (const float*)d_in[11];
    const float* ln_g   = (const float*)d_in[12];
    const float* ln_b   = (const float*)d_in[13];
    const float* head_w = (const float*)d_in[14];
    const float* head_b = (const float*)d_in[15];
    float* out = (float*)d_out;

    float *hbuf, *xzbuf;
    __nv_bfloat16 *whi, *wlo, *xhi, *xlo, *hhi, *hlo, *yhi, *ylo;
    cudaGetSymbolAddress((void**)&hbuf,  g_h);
    cudaGetSymbolAddress((void**)&xzbuf, g_xz);
    cudaGetSymbolAddress((void**)&whi,   g_whi);
    cudaGetSymbolAddress((void**)&wlo,   g_wlo);
    cudaGetSymbolAddress((void**)&xhi,   g_xhi);
    cudaGetSymbolAddress((void**)&xlo,   g_xlo);
    cudaGetSymbolAddress((void**)&hhi,   g_hhi);
    cudaGetSymbolAddress((void**)&hlo,   g_hlo);
    cudaGetSymbolAddress((void**)&yhi,   g_yhi);
    cudaGetSymbolAddress((void**)&ylo,   g_ylo);

    __nv_bfloat16* whi_proj = whi;
    __nv_bfloat16* wlo_proj = wlo;
    __nv_bfloat16* whi_ipw  = whi + 16384;
    __nv_bfloat16* wlo_ipw  = wlo + 16384;
    __nv_bfloat16* whi_opw  = whi + 1064960;
    __nv_bfloat16* wlo_opw  = wlo + 1064960;

    // weights -> bf16 hi/lo
    split_kernel<<<64, 256>>>(proj_w, whi_proj, wlo_proj, 16384);
    split_kernel<<<4096, 256>>>(ipw, whi_ipw, wlo_ipw, 1048576);
    split_kernel<<<2048, 256>>>(opw, whi_opw, wlo_opw, 524288);
    // input x -> bf16 hi/lo
    split_kernel<<<2048, 256>>>(x, xhi, xlo, 524288);

    dim3 grid_in(2, 64);      // N=256/128,  M=8192/128
    dim3 grid_ip(8, 64);      // N=1024/128
    dim3 grid_op(2, 64);      // N=256/128
    dim3 grid_sc(32, 8);      // channel groups x batches

    // input projection: h = x @ proj_w^T + proj_b   [8192,256], K=64
    wgemm_nt_kernel<<<grid_in, 256>>>(xhi, xlo, whi_proj, wlo_proj, hbuf,
                                      BT, DMv, Fv);
    bias_add_kernel<<<8192, 256>>>(hbuf, proj_b, BT * DMv);
    split_kernel<<<8192, 256>>>(hbuf, hhi, hlo, BT * DMv);

    for (int l = 0; l < Lv; ++l) {
        const size_t ipoff = (size_t)l * 262144;   // (2*DIv)*DMv
        const size_t opoff = (size_t)l * 131072;   // DMv*DIv

        // in_proj: xz = h @ ipw^T   [8192,1024], K=256
        wgemm_nt_kernel<<<grid_ip, 256>>>(hhi, hlo,
                                          whi_ipw + ipoff, wlo_ipw + ipoff,
                                          xzbuf, BT, 2*DIv, DMv);

        fused_mid_kernel<<<512, 256>>>(
            cw  + (size_t)l * DIv * DCv,
            cb  + (size_t)l * DIv,
            xpw + (size_t)l * (DTRv + 2*Nv) * DIv,
            dtw + (size_t)l * DIv * DTRv,
            dtb + (size_t)l * DIv);

        scan2_kernel<<<grid_sc, 256>>>(A_log + (size_t)l * DIv * Nv,
                                       Dp    + (size_t)l * DIv);

        // out_proj: h = y @ opw^T   [8192,256], K=512
        wgemm_nt_kernel<<<grid_op, 256>>>(yhi, ylo,
                                          whi_opw + opoff, wlo_opw + opoff,
                                          hbuf, BT, DMv, DIv);

        if (l < Lv - 1)
            split_kernel<<<8192, 256>>>(hbuf, hhi, hlo, BT * DMv);
    }

    final_kernel<<<Bv, 256>>>(ln_g, ln_b, head_w, head_b, out);
}